// round 10
// baseline (speedup 1.0000x reference)
#include <cuda_runtime.h>
#include <cstdint>

#define N_GAUSS 4096
#define NSLICE  4
#define EPSF    1e-6f
// +0.5 * log2(e)
#define HL2E    0.72134752044448170367996234050095f
// contiguous pixel x step
#define HPIX    (2.0f / 127.0f)
#define SA_THIN 40.0f

// table: per (slice, subchunk) of 128 pairs, 32 floats per pair (128B line):
// [2e+h]: e0 SA, e1 E, e2 SM(-SA*mx), e3 NCp(-Cp), e4 NMY(-my), e5 OP,
//         e6 OFT, e7 DC(-2*Delta), e8 DD(-Delta^2), e9 R(2^-2Delta^2)
__device__ __align__(16) float g_table[NSLICE * 16 * 128 * 32];
__device__ int g_nsafe_pairs[16];                 // slice-invariant
__device__ float2 g_partial[NSLICE * 16 * 16384]; // per (slice,sub,pixel)
__device__ unsigned g_tile_done[NSLICE * 16];     // zero-init; wraps to 0

// ---------------------------------------------------------------------------
__device__ __forceinline__ uint64_t pk2(float lo, float hi) {
    uint64_t r;
    asm("mov.b64 %0, {%1,%2};" : "=l"(r) : "f"(lo), "f"(hi));
    return r;
}
__device__ __forceinline__ void upk2(uint64_t v, float& lo, float& hi) {
    asm("mov.b64 {%0,%1}, %2;" : "=f"(lo), "=f"(hi) : "l"(v));
}
__device__ __forceinline__ uint64_t fma2(uint64_t a, uint64_t b, uint64_t c) {
    uint64_t d;
    asm("fma.rn.f32x2 %0, %1, %2, %3;" : "=l"(d) : "l"(a), "l"(b), "l"(c));
    return d;
}
__device__ __forceinline__ uint64_t mul2(uint64_t a, uint64_t b) {
    uint64_t d;
    asm("mul.rn.f32x2 %0, %1, %2;" : "=l"(d) : "l"(a), "l"(b));
    return d;
}
__device__ __forceinline__ uint64_t add2(uint64_t a, uint64_t b) {
    uint64_t d;
    asm("add.rn.f32x2 %0, %1, %2;" : "=l"(d) : "l"(a), "l"(b));
    return d;
}
__device__ __forceinline__ float ex2a(float x) {
    float r;
    asm("ex2.approx.f32 %0, %1;" : "=f"(r) : "f"(x));
    return r;
}

// ---------------------------------------------------------------------------
// Kernel 1: precompute. One thread per gaussian (16 blocks x 256 = subchunk
// per block). Heavy math + partition done once; 4 slice entries written.
// ---------------------------------------------------------------------------
__global__ void __launch_bounds__(256) k_precompute(
        const float* __restrict__ means,
        const float* __restrict__ scales,
        const float* __restrict__ rot,
        const float* __restrict__ opac,
        const float* __restrict__ feat) {
    __shared__ float red[8];
    __shared__ int wsum[8];

    int sub = blockIdx.x;        // 16 blocks, one subchunk each
    int t   = threadIdx.x;
    int lane = t & 31;
    int wid  = t >> 5;

    // block-local max over all 4096 z-scales
    {
        float m = 0.0f;
        for (int k = t; k < N_GAUSS; k += 256)
            m = fmaxf(m, __ldg(&scales[k * 3 + 2]));
#pragma unroll
        for (int o = 16; o > 0; o >>= 1)
            m = fmaxf(m, __shfl_xor_sync(0xffffffffu, m, o));
        if (lane == 0) red[wid] = m;
    }
    __syncthreads();
    float md = red[0];
#pragma unroll
    for (int u = 1; u < 8; u++) md = fmaxf(md, red[u]);
    md *= 3.0f;

    int k = sub * 256 + t;

    float4 q4 = __ldg(reinterpret_cast<const float4*>(rot) + k);
    float inq = rsqrtf(q4.x * q4.x + q4.y * q4.y + q4.z * q4.z + q4.w * q4.w);
    float w = q4.x * inq, x = q4.y * inq, y = q4.z * inq, z = q4.w * inq;

    float r00 = 1.f - 2.f * (y * y + z * z);
    float r01 = 2.f * (x * y - w * z);
    float r02 = 2.f * (x * z + w * y);
    float r10 = 2.f * (x * y + w * z);
    float r11 = 1.f - 2.f * (x * x + z * z);
    float r12 = 2.f * (y * z - w * x);
    float r20 = 2.f * (x * z - w * y);
    float r21 = 2.f * (y * z + w * x);
    float r22 = 1.f - 2.f * (x * x + y * y);

    float sx = scales[k * 3 + 0], sy = scales[k * 3 + 1], sz = scales[k * 3 + 2];
    float m00 = r00 * sx, m01 = r01 * sy, m02 = r02 * sz;
    float m10 = r10 * sx, m11 = r11 * sy, m12 = r12 * sz;
    float m20 = r20 * sx, m21 = r21 * sy, m22 = r22 * sz;

    float c00 = m00 * m00 + m01 * m01 + m02 * m02;
    float c01 = m00 * m10 + m01 * m11 + m02 * m12;
    float c11 = m10 * m10 + m11 * m11 + m12 * m12;
    float c02 = m00 * m20 + m01 * m21 + m02 * m22;
    float c12 = m10 * m20 + m11 * m21 + m12 * m22;
    float c22 = m20 * m20 + m21 * m21 + m22 * m22;

    float szz = c22 + EPSF;
    float rx = c02 / szz;
    float ry = c12 / szz;

    float s00 = c00 - c02 * c02 / szz + EPSF;
    float s01 = c01 - c02 * c12 / szz;
    float s11 = c11 - c12 * c12 / szz + EPSF;
    float det = s00 * s11 - s01 * s01;
    float A  = s11 / det;
    float Bc = -s01 / det;
    float D  = s00 / det;

    float a = HL2E * A;
    float b = HL2E * 2.0f * Bc;
    float c = HL2E * D;
    float SA = sqrtf(a);
    float E  = b / (2.0f * SA);
    float Cp = c - E * E;
    if (Cp < 0.0f) Cp = 0.0f;

    float Delta = SA * HPIX;
    float DC = -2.0f * Delta;
    float DD = -Delta * Delta;
    float R  = ex2a(2.0f * DD);

    int safe = (SA <= SA_THIN) ? 1 : 0;

    // block-wide stable partition: safe gaussians first
    unsigned bal = __ballot_sync(0xffffffffu, safe);
    unsigned ltmask = (1u << lane) - 1u;
    int w_safe_pre = __popc(bal & ltmask);
    int w_safe_tot = __popc(bal);
    if (lane == 0) wsum[wid] = w_safe_tot;
    __syncthreads();
    int safe_off = 0, n_safe = 0;
#pragma unroll
    for (int u = 0; u < 8; u++) {
        int v2 = wsum[u];
        if (u < wid) safe_off += v2;
        n_safe += v2;
    }
    int thin_off = n_safe + (32 * wid - safe_off);
    int pos = safe ? (safe_off + w_safe_pre)
                   : (thin_off + (lane - w_safe_pre));

    if (t == 0) g_nsafe_pairs[sub] = n_safe >> 1;

    float mx0 = means[k * 3 + 0], my0 = means[k * 3 + 1], mz = means[k * 3 + 2];
    float op = opac[k];
    float ft = feat[k];

    int kp = pos >> 1;
    int h  = pos & 1;

#pragma unroll
    for (int s = 0; s < NSLICE; s++) {
        float zs = -0.15f + 0.1f * (float)s;
        float zoff = zs - mz;
        float mx = mx0 + rx * zoff;
        float my = my0 + ry * zoff;
        float mask = (fabsf(mz - zs) < md) ? 1.0f : 0.0f;

        float* tp = g_table + ((size_t)((s * 16 + sub) * 128 + kp) * 32);
        tp[0  + h] = SA;
        tp[2  + h] = E;
        tp[4  + h] = -SA * mx;
        tp[6  + h] = -Cp;
        tp[8  + h] = -my;
        tp[10 + h] = mask * op;
        tp[12 + h] = mask * op * ft;
        tp[14 + h] = DC;
        tp[16 + h] = DD;
        tp[18 + h] = R;
    }
}

// ---------------------------------------------------------------------------
// Kernel 2: partial render + fused fold.
// Block = one (slice, subchunk, 8-row tile). 128 threads; 8 contiguous
// pixels per thread; exp recurrence across pixels.
// Last-arriving block per (slice, tile) folds the 16 subchunk partials
// into the output (threadfence-reduction pattern).
// grid = 1024 = 4 slices * 16 subchunks * 16 tiles.
// ---------------------------------------------------------------------------
__global__ void __launch_bounds__(128, 7) k_render_part(float* __restrict__ out) {
    __shared__ __align__(16) uint4 smt[1024];   // 128 pairs * 128B = 16KB
    __shared__ int lastflag;

    int bid  = blockIdx.x;
    int s    = bid >> 8;
    int sub  = (bid >> 4) & 15;
    int tile = bid & 15;
    int tid  = threadIdx.x;

    const uint4* gsrc = reinterpret_cast<const uint4*>(g_table)
                        + (size_t)(s * 16 + sub) * 128 * 8;
#pragma unroll 8
    for (int t = tid; t < 1024; t += 128)
        smt[t] = __ldg(gsrc + t);
    int nsp = __ldg(&g_nsafe_pairs[sub]);
    __syncthreads();

    int i  = tile * 8 + (tid >> 4);      // row
    int jb = (tid & 15) * 8;             // first col of this thread's 8

    float yv = -1.0f + (float)i * (2.0f / 127.0f);
    float x0 = -1.0f + (float)jb * HPIX;

    uint64_t Y  = pk2(yv, yv);
    uint64_t X0 = pk2(x0, x0);
    const uint64_t SGN = 0x8000000080000000ULL;

    uint64_t S1[8], S2[8];
#pragma unroll
    for (int p = 0; p < 8; p++) { S1[p] = pk2(0.f, 0.f); S2[p] = pk2(0.f, 0.f); }

    const ulonglong2* sp = reinterpret_cast<const ulonglong2*>(smt);

    int kp = 0;
    // ---- safe pairs: 2 exp-pairs per pair-row, multiplicative chain ----
#pragma unroll 2
    for (; kp < nsp; kp++) {
        ulonglong2 u0 = sp[kp * 8 + 0];   // SA | E
        ulonglong2 u1 = sp[kp * 8 + 1];   // SM | NCp
        ulonglong2 u2 = sp[kp * 8 + 2];   // NMY | OP
        ulonglong2 u3 = sp[kp * 8 + 3];   // OFT | DC
        ulonglong2 u4 = sp[kp * 8 + 4];   // DD | R

        uint64_t dy = add2(Y, u2.x);
        uint64_t wv = mul2(mul2(u1.y, dy), dy);   // -Cp*dy^2 <= 0
        uint64_t v  = fma2(u0.x, X0, u1.x);       // SA*x0 + SM
        v = fma2(u0.y, dy, v);                    // + E*dy
        uint64_t nv = v ^ SGN;
        uint64_t q0 = fma2(v, nv, wv);            // -L0
        uint64_t qd = fma2(u3.y, v, u4.x);        // DC*v0 + DD

        float a2, b2, c2, d2;
        upk2(qd, a2, b2);
        a2 = fminf(a2, 88.0f);
        b2 = fminf(b2, 88.0f);
        upk2(q0, c2, d2);
        uint64_t g = pk2(ex2a(c2), ex2a(d2));
        uint64_t d = pk2(ex2a(a2), ex2a(b2));
        uint64_t R = u4.y;

#pragma unroll
        for (int p = 0; p < 8; p++) {
            S2[p] = fma2(g, u2.y, S2[p]);
            uint64_t gg = mul2(g, g);
            S1[p] = fma2(gg, u3.x, S1[p]);
            if (p < 7) {
                g = mul2(g, d);
                d = mul2(d, R);
            }
        }
    }
    // ---- thin pairs: exact ex2 per pixel ----
    for (; kp < 128; kp++) {
        ulonglong2 u0 = sp[kp * 8 + 0];
        ulonglong2 u1 = sp[kp * 8 + 1];
        ulonglong2 u2 = sp[kp * 8 + 2];
        ulonglong2 u3 = sp[kp * 8 + 3];

        uint64_t dy = add2(Y, u2.x);
        uint64_t wv = mul2(mul2(u1.y, dy), dy);
        uint64_t v  = fma2(u0.x, X0, u1.x);
        v = fma2(u0.y, dy, v);
        uint64_t dl = mul2(u3.y, pk2(-0.5f, -0.5f));

#pragma unroll
        for (int p = 0; p < 8; p++) {
            uint64_t nv = v ^ SGN;
            uint64_t q  = fma2(v, nv, wv);
            float l, h;
            upk2(q, l, h);
            uint64_t g = pk2(ex2a(l), ex2a(h));
            S2[p] = fma2(g, u2.y, S2[p]);
            uint64_t gg = mul2(g, g);
            S1[p] = fma2(gg, u3.x, S1[p]);
            v = add2(v, dl);
        }
    }

    // ---- write partials ----
    int p0 = i * 128 + jb;
    float2* dst = g_partial + (size_t)(s * 16 + sub) * 16384;
#pragma unroll
    for (int p = 0; p < 8; p++) {
        float s1l, s1h, s2l, s2h;
        upk2(S1[p], s1l, s1h);
        upk2(S2[p], s2l, s2h);
        dst[p0 + p] = make_float2(s1l + s1h, s2l + s2h);
    }

    // ---- fused fold: last block per (slice, tile) combines subchunks ----
    __threadfence();
    __syncthreads();
    if (tid == 0) {
        unsigned old = atomicInc(&g_tile_done[s * 16 + tile], 15u);
        lastflag = (old == 15u);
    }
    __syncthreads();
    if (lastflag) {
        __threadfence();
        const float2* base = g_partial + (size_t)s * 16 * 16384 + p0;
        float img[8], T[8];
#pragma unroll
        for (int p = 0; p < 8; p++) { img[p] = 0.0f; T[p] = 1.0f; }
#pragma unroll
        for (int c = 0; c < 4; c++) {
            float S1s[8], S2s[8];
#pragma unroll
            for (int p = 0; p < 8; p++) { S1s[p] = 0.0f; S2s[p] = 0.0f; }
#pragma unroll
            for (int u = 0; u < 4; u++) {
                const float2* src = base + (size_t)(c * 4 + u) * 16384;
#pragma unroll
                for (int p = 0; p < 8; p += 2) {
                    float4 v2 = __ldg(reinterpret_cast<const float4*>(src + p));
                    S1s[p]     += v2.x;  S2s[p]     += v2.y;
                    S1s[p + 1] += v2.z;  S2s[p + 1] += v2.w;
                }
            }
#pragma unroll
            for (int p = 0; p < 8; p++) {
                img[p] = fmaf(T[p], S1s[p], img[p]);
                T[p]   = T[p] * (1.0f - S2s[p]);
            }
        }
        float* o = out + (size_t)s * 16384 + p0;
#pragma unroll
        for (int p = 0; p < 8; p++) o[p] = img[p];   // BACKGROUND == 0
    }
}

// ---------------------------------------------------------------------------
extern "C" void kernel_launch(void* const* d_in, const int* in_sizes, int n_in,
                              void* d_out, int out_size) {
    const float* means  = (const float*)d_in[0];
    const float* scales = (const float*)d_in[1];
    const float* rots   = (const float*)d_in[2];
    const float* opac   = (const float*)d_in[3];
    const float* feat   = (const float*)d_in[4];
    float* out = (float*)d_out;

    k_precompute<<<16, 256>>>(means, scales, rots, opac, feat);
    k_render_part<<<1024, 128>>>(out);
}

// round 11
// speedup vs baseline: 1.0751x; 1.0751x over previous
#include <cuda_runtime.h>
#include <cstdint>

#define N_GAUSS 4096
#define NSLICE  4
#define EPSF    1e-6f
// +0.5 * log2(e)
#define HL2E    0.72134752044448170367996234050095f
// contiguous pixel x step
#define HPIX    (2.0f / 127.0f)
#define SA_THIN 40.0f

// table: per (slice, subchunk) of 128 pairs, 32 floats per pair (128B line):
// [2e+h]: e0 SA, e1 E, e2 SM(-SA*mx), e3 NCp(-Cp), e4 NMY(-my), e5 OP,
//         e6 OFT, e7 DC(-2*Delta), e8 DD(-Delta^2), e9 R(2^-2Delta^2)
__device__ __align__(16) float g_table[NSLICE * 16 * 128 * 32];
__device__ int g_nsafe_pairs[16];                 // slice-invariant
__device__ float2 g_partial[NSLICE * 16 * 16384]; // per (slice,sub,pixel)

// ---------------------------------------------------------------------------
__device__ __forceinline__ uint64_t pk2(float lo, float hi) {
    uint64_t r;
    asm("mov.b64 %0, {%1,%2};" : "=l"(r) : "f"(lo), "f"(hi));
    return r;
}
__device__ __forceinline__ void upk2(uint64_t v, float& lo, float& hi) {
    asm("mov.b64 {%0,%1}, %2;" : "=f"(lo), "=f"(hi) : "l"(v));
}
__device__ __forceinline__ uint64_t fma2(uint64_t a, uint64_t b, uint64_t c) {
    uint64_t d;
    asm("fma.rn.f32x2 %0, %1, %2, %3;" : "=l"(d) : "l"(a), "l"(b), "l"(c));
    return d;
}
__device__ __forceinline__ uint64_t mul2(uint64_t a, uint64_t b) {
    uint64_t d;
    asm("mul.rn.f32x2 %0, %1, %2;" : "=l"(d) : "l"(a), "l"(b));
    return d;
}
__device__ __forceinline__ uint64_t add2(uint64_t a, uint64_t b) {
    uint64_t d;
    asm("add.rn.f32x2 %0, %1, %2;" : "=l"(d) : "l"(a), "l"(b));
    return d;
}
__device__ __forceinline__ float ex2a(float x) {
    float r;
    asm("ex2.approx.f32 %0, %1;" : "=f"(r) : "f"(x));
    return r;
}

// ---------------------------------------------------------------------------
// Kernel 1: precompute. One thread per gaussian (16 blocks x 256 = subchunk
// per block). Heavy math + partition done once; 4 slice entries written.
// ---------------------------------------------------------------------------
__global__ void __launch_bounds__(256) k_precompute(
        const float* __restrict__ means,
        const float* __restrict__ scales,
        const float* __restrict__ rot,
        const float* __restrict__ opac,
        const float* __restrict__ feat) {
    __shared__ float red[8];
    __shared__ int wsum[8];

    int sub = blockIdx.x;        // 16 blocks, one subchunk each
    int t   = threadIdx.x;
    int lane = t & 31;
    int wid  = t >> 5;

    // block-local max over all 4096 z-scales
    {
        float m = 0.0f;
        for (int k = t; k < N_GAUSS; k += 256)
            m = fmaxf(m, __ldg(&scales[k * 3 + 2]));
#pragma unroll
        for (int o = 16; o > 0; o >>= 1)
            m = fmaxf(m, __shfl_xor_sync(0xffffffffu, m, o));
        if (lane == 0) red[wid] = m;
    }
    __syncthreads();
    float md = red[0];
#pragma unroll
    for (int u = 1; u < 8; u++) md = fmaxf(md, red[u]);
    md *= 3.0f;

    int k = sub * 256 + t;

    float4 q4 = __ldg(reinterpret_cast<const float4*>(rot) + k);
    float inq = rsqrtf(q4.x * q4.x + q4.y * q4.y + q4.z * q4.z + q4.w * q4.w);
    float w = q4.x * inq, x = q4.y * inq, y = q4.z * inq, z = q4.w * inq;

    float r00 = 1.f - 2.f * (y * y + z * z);
    float r01 = 2.f * (x * y - w * z);
    float r02 = 2.f * (x * z + w * y);
    float r10 = 2.f * (x * y + w * z);
    float r11 = 1.f - 2.f * (x * x + z * z);
    float r12 = 2.f * (y * z - w * x);
    float r20 = 2.f * (x * z - w * y);
    float r21 = 2.f * (y * z + w * x);
    float r22 = 1.f - 2.f * (x * x + y * y);

    float sx = scales[k * 3 + 0], sy = scales[k * 3 + 1], sz = scales[k * 3 + 2];
    float m00 = r00 * sx, m01 = r01 * sy, m02 = r02 * sz;
    float m10 = r10 * sx, m11 = r11 * sy, m12 = r12 * sz;
    float m20 = r20 * sx, m21 = r21 * sy, m22 = r22 * sz;

    float c00 = m00 * m00 + m01 * m01 + m02 * m02;
    float c01 = m00 * m10 + m01 * m11 + m02 * m12;
    float c11 = m10 * m10 + m11 * m11 + m12 * m12;
    float c02 = m00 * m20 + m01 * m21 + m02 * m22;
    float c12 = m10 * m20 + m11 * m21 + m12 * m22;
    float c22 = m20 * m20 + m21 * m21 + m22 * m22;

    float szz = c22 + EPSF;
    float rx = c02 / szz;
    float ry = c12 / szz;

    float s00 = c00 - c02 * c02 / szz + EPSF;
    float s01 = c01 - c02 * c12 / szz;
    float s11 = c11 - c12 * c12 / szz + EPSF;
    float det = s00 * s11 - s01 * s01;
    float A  = s11 / det;
    float Bc = -s01 / det;
    float D  = s00 / det;

    float a = HL2E * A;
    float b = HL2E * 2.0f * Bc;
    float c = HL2E * D;
    float SA = sqrtf(a);
    float E  = b / (2.0f * SA);
    float Cp = c - E * E;
    if (Cp < 0.0f) Cp = 0.0f;

    float Delta = SA * HPIX;
    float DC = -2.0f * Delta;
    float DD = -Delta * Delta;
    float R  = ex2a(2.0f * DD);

    int safe = (SA <= SA_THIN) ? 1 : 0;

    // block-wide stable partition: safe gaussians first
    unsigned bal = __ballot_sync(0xffffffffu, safe);
    unsigned ltmask = (1u << lane) - 1u;
    int w_safe_pre = __popc(bal & ltmask);
    int w_safe_tot = __popc(bal);
    if (lane == 0) wsum[wid] = w_safe_tot;
    __syncthreads();
    int safe_off = 0, n_safe = 0;
#pragma unroll
    for (int u = 0; u < 8; u++) {
        int v2 = wsum[u];
        if (u < wid) safe_off += v2;
        n_safe += v2;
    }
    int thin_off = n_safe + (32 * wid - safe_off);
    int pos = safe ? (safe_off + w_safe_pre)
                   : (thin_off + (lane - w_safe_pre));

    if (t == 0) g_nsafe_pairs[sub] = n_safe >> 1;

    float mx0 = means[k * 3 + 0], my0 = means[k * 3 + 1], mz = means[k * 3 + 2];
    float op = opac[k];
    float ft = feat[k];

    int kp = pos >> 1;
    int h  = pos & 1;

#pragma unroll
    for (int s = 0; s < NSLICE; s++) {
        float zs = -0.15f + 0.1f * (float)s;
        float zoff = zs - mz;
        float mx = mx0 + rx * zoff;
        float my = my0 + ry * zoff;
        float mask = (fabsf(mz - zs) < md) ? 1.0f : 0.0f;

        float* tp = g_table + ((size_t)((s * 16 + sub) * 128 + kp) * 32);
        tp[0  + h] = SA;
        tp[2  + h] = E;
        tp[4  + h] = -SA * mx;
        tp[6  + h] = -Cp;
        tp[8  + h] = -my;
        tp[10 + h] = mask * op;
        tp[12 + h] = mask * op * ft;
        tp[14 + h] = DC;
        tp[16 + h] = DD;
        tp[18 + h] = R;
    }
}

// ---------------------------------------------------------------------------
// Kernel 2: partial render with exp recurrence along 8 contiguous pixels.
// Block = one (slice, subchunk, 8-row tile). 128 threads; 8 contiguous
// pixels per thread. grid = 1024 = 4 slices * 16 subchunks * 16 tiles.
// ---------------------------------------------------------------------------
__global__ void __launch_bounds__(128, 7) k_render_part() {
    __shared__ __align__(16) uint4 smt[1024];   // 128 pairs * 128B = 16KB

    int bid  = blockIdx.x;
    int s    = bid >> 8;
    int sub  = (bid >> 4) & 15;
    int tile = bid & 15;
    int tid  = threadIdx.x;

    const uint4* gsrc = reinterpret_cast<const uint4*>(g_table)
                        + (size_t)(s * 16 + sub) * 128 * 8;
#pragma unroll 8
    for (int t = tid; t < 1024; t += 128)
        smt[t] = __ldg(gsrc + t);
    int nsp = __ldg(&g_nsafe_pairs[sub]);
    __syncthreads();

    int i  = tile * 8 + (tid >> 4);      // row
    int jb = (tid & 15) * 8;             // first col of this thread's 8

    float yv = -1.0f + (float)i * (2.0f / 127.0f);
    float x0 = -1.0f + (float)jb * HPIX;

    uint64_t Y  = pk2(yv, yv);
    uint64_t X0 = pk2(x0, x0);
    const uint64_t SGN = 0x8000000080000000ULL;

    uint64_t S1[8], S2[8];
#pragma unroll
    for (int p = 0; p < 8; p++) { S1[p] = pk2(0.f, 0.f); S2[p] = pk2(0.f, 0.f); }

    const ulonglong2* sp = reinterpret_cast<const ulonglong2*>(smt);

    int kp = 0;
    // ---- safe pairs: 2 exp-pairs per pair-row, multiplicative chain ----
#pragma unroll 2
    for (; kp < nsp; kp++) {
        ulonglong2 u0 = sp[kp * 8 + 0];   // SA | E
        ulonglong2 u1 = sp[kp * 8 + 1];   // SM | NCp
        ulonglong2 u2 = sp[kp * 8 + 2];   // NMY | OP
        ulonglong2 u3 = sp[kp * 8 + 3];   // OFT | DC
        ulonglong2 u4 = sp[kp * 8 + 4];   // DD | R

        uint64_t dy = add2(Y, u2.x);
        uint64_t wv = mul2(mul2(u1.y, dy), dy);   // -Cp*dy^2 <= 0
        uint64_t v  = fma2(u0.x, X0, u1.x);       // SA*x0 + SM
        v = fma2(u0.y, dy, v);                    // + E*dy
        uint64_t nv = v ^ SGN;
        uint64_t q0 = fma2(v, nv, wv);            // -L0
        uint64_t qd = fma2(u3.y, v, u4.x);        // DC*v0 + DD

        float a2, b2, c2, d2;
        upk2(qd, a2, b2);
        a2 = fminf(a2, 88.0f);
        b2 = fminf(b2, 88.0f);
        upk2(q0, c2, d2);
        uint64_t g = pk2(ex2a(c2), ex2a(d2));
        uint64_t d = pk2(ex2a(a2), ex2a(b2));
        uint64_t R = u4.y;

#pragma unroll
        for (int p = 0; p < 8; p++) {
            S2[p] = fma2(g, u2.y, S2[p]);
            uint64_t gg = mul2(g, g);
            S1[p] = fma2(gg, u3.x, S1[p]);
            if (p < 7) {
                g = mul2(g, d);
                d = mul2(d, R);
            }
        }
    }
    // ---- thin pairs: exact ex2 per pixel ----
    for (; kp < 128; kp++) {
        ulonglong2 u0 = sp[kp * 8 + 0];
        ulonglong2 u1 = sp[kp * 8 + 1];
        ulonglong2 u2 = sp[kp * 8 + 2];
        ulonglong2 u3 = sp[kp * 8 + 3];

        uint64_t dy = add2(Y, u2.x);
        uint64_t wv = mul2(mul2(u1.y, dy), dy);
        uint64_t v  = fma2(u0.x, X0, u1.x);
        v = fma2(u0.y, dy, v);
        uint64_t dl = mul2(u3.y, pk2(-0.5f, -0.5f));

#pragma unroll
        for (int p = 0; p < 8; p++) {
            uint64_t nv = v ^ SGN;
            uint64_t q  = fma2(v, nv, wv);
            float l, h;
            upk2(q, l, h);
            uint64_t g = pk2(ex2a(l), ex2a(h));
            S2[p] = fma2(g, u2.y, S2[p]);
            uint64_t gg = mul2(g, g);
            S1[p] = fma2(gg, u3.x, S1[p]);
            v = add2(v, dl);
        }
    }

    // ---- write partials ----
    int p0 = i * 128 + jb;
    float2* dst = g_partial + (size_t)(s * 16 + sub) * 16384;
#pragma unroll
    for (int p = 0; p < 8; p++) {
        float s1l, s1h, s2l, s2h;
        upk2(S1[p], s1l, s1h);
        upk2(S2[p], s2l, s2h);
        dst[p0 + p] = make_float2(s1l + s1h, s2l + s2h);
    }
}

// ---------------------------------------------------------------------------
// Kernel 3: fold. 2 pixels per thread via float4 loads (16 independent
// loads, MLP-16); subchunk pair-adds then exact 4-chunk transmittance
// recurrence (== reference scan). 128 blocks x 256 threads.
// ---------------------------------------------------------------------------
__global__ void __launch_bounds__(256) k_fold(float* __restrict__ out) {
    int g = blockIdx.x * 256 + threadIdx.x;   // 32768
    int s  = g >> 13;
    int pp = g & 8191;                        // pixel pair
    const float4* base = reinterpret_cast<const float4*>(
        g_partial + (size_t)s * 16 * 16384) + pp;

    float img0 = 0.0f, T0 = 1.0f, img1 = 0.0f, T1 = 1.0f;
#pragma unroll
    for (int c = 0; c < 4; c++) {
        float S1a = 0.0f, S2a = 0.0f, S1b = 0.0f, S2b = 0.0f;
#pragma unroll
        for (int u = 0; u < 4; u++) {
            float4 v = __ldg(base + (size_t)(c * 4 + u) * 8192);
            S1a += v.x;  S2a += v.y;
            S1b += v.z;  S2b += v.w;
        }
        img0 = fmaf(T0, S1a, img0);
        T0   = T0 * (1.0f - S2a);
        img1 = fmaf(T1, S1b, img1);
        T1   = T1 * (1.0f - S2b);
    }
    float2* o = reinterpret_cast<float2*>(out + (size_t)s * 16384) + pp;
    *o = make_float2(img0, img1);   // BACKGROUND == 0
}

// ---------------------------------------------------------------------------
extern "C" void kernel_launch(void* const* d_in, const int* in_sizes, int n_in,
                              void* d_out, int out_size) {
    const float* means  = (const float*)d_in[0];
    const float* scales = (const float*)d_in[1];
    const float* rots   = (const float*)d_in[2];
    const float* opac   = (const float*)d_in[3];
    const float* feat   = (const float*)d_in[4];
    float* out = (float*)d_out;

    k_precompute<<<16, 256>>>(means, scales, rots, opac, feat);
    k_render_part<<<1024, 128>>>();
    k_fold<<<128, 256>>>(out);
}

// round 12
// speedup vs baseline: 1.1048x; 1.0276x over previous
#include <cuda_runtime.h>
#include <cstdint>

#define N_GAUSS 4096
#define NSLICE  4
#define EPSF    1e-6f
// +0.5 * log2(e)
#define HL2E    0.72134752044448170367996234050095f
// contiguous pixel x step
#define HPIX    (2.0f / 127.0f)
#define SA_THIN 40.0f

// table: per (slice, subchunk) of 128 pairs, 32 floats per pair (128B line):
// [2e+h]: e0 SA, e1 E, e2 SM(-SA*mx), e3 NCp(-Cp), e4 NMY(-my), e5 OP,
//         e6 OFT, e7 DC(-2*Delta), e8 DD(-Delta^2), e9 R(2^-2Delta^2)
__device__ __align__(16) float g_table[NSLICE * 16 * 128 * 32];
__device__ int g_nsafe_pairs[16];                 // slice-invariant
__device__ float2 g_partial[NSLICE * 16 * 16384]; // per (slice,sub,pixel)

// ---------------------------------------------------------------------------
__device__ __forceinline__ uint64_t pk2(float lo, float hi) {
    uint64_t r;
    asm("mov.b64 %0, {%1,%2};" : "=l"(r) : "f"(lo), "f"(hi));
    return r;
}
__device__ __forceinline__ void upk2(uint64_t v, float& lo, float& hi) {
    asm("mov.b64 {%0,%1}, %2;" : "=f"(lo), "=f"(hi) : "l"(v));
}
__device__ __forceinline__ uint64_t fma2(uint64_t a, uint64_t b, uint64_t c) {
    uint64_t d;
    asm("fma.rn.f32x2 %0, %1, %2, %3;" : "=l"(d) : "l"(a), "l"(b), "l"(c));
    return d;
}
__device__ __forceinline__ uint64_t mul2(uint64_t a, uint64_t b) {
    uint64_t d;
    asm("mul.rn.f32x2 %0, %1, %2;" : "=l"(d) : "l"(a), "l"(b));
    return d;
}
__device__ __forceinline__ uint64_t add2(uint64_t a, uint64_t b) {
    uint64_t d;
    asm("add.rn.f32x2 %0, %1, %2;" : "=l"(d) : "l"(a), "l"(b));
    return d;
}
__device__ __forceinline__ float ex2a(float x) {
    float r;
    asm("ex2.approx.f32 %0, %1;" : "=f"(r) : "f"(x));
    return r;
}

// ---------------------------------------------------------------------------
// Kernel 1: precompute. 64 blocks = (slice, subchunk), 256 threads = one
// gaussian each. Coefficients staged in smem, then written to g_table as
// fully-coalesced uint4 (the old direct writes were 128B-strided scatters
// and dominated this kernel's runtime).
// ---------------------------------------------------------------------------
__global__ void __launch_bounds__(256) k_precompute(
        const float* __restrict__ means,
        const float* __restrict__ scales,
        const float* __restrict__ rot,
        const float* __restrict__ opac,
        const float* __restrict__ feat) {
    __shared__ float red[8];
    __shared__ int wsum[8];
    __shared__ __align__(16) float stg[128 * 32];   // 16KB staging tile

    int s   = blockIdx.x >> 4;
    int sub = blockIdx.x & 15;
    int t   = threadIdx.x;
    int lane = t & 31;
    int wid  = t >> 5;

    // zero staging (pads must be deterministic)
    {
        uint4 z = make_uint4(0, 0, 0, 0);
        uint4* sz4 = reinterpret_cast<uint4*>(stg);
#pragma unroll 4
        for (int u = t; u < 1024; u += 256) sz4[u] = z;
    }

    // block-local max over all 4096 z-scales
    {
        float m = 0.0f;
        for (int k = t; k < N_GAUSS; k += 256)
            m = fmaxf(m, __ldg(&scales[k * 3 + 2]));
#pragma unroll
        for (int o = 16; o > 0; o >>= 1)
            m = fmaxf(m, __shfl_xor_sync(0xffffffffu, m, o));
        if (lane == 0) red[wid] = m;
    }
    __syncthreads();
    float md = red[0];
#pragma unroll
    for (int u = 1; u < 8; u++) md = fmaxf(md, red[u]);
    md *= 3.0f;

    int k = sub * 256 + t;

    float4 q4 = __ldg(reinterpret_cast<const float4*>(rot) + k);
    float inq = rsqrtf(q4.x * q4.x + q4.y * q4.y + q4.z * q4.z + q4.w * q4.w);
    float w = q4.x * inq, x = q4.y * inq, y = q4.z * inq, z = q4.w * inq;

    float r00 = 1.f - 2.f * (y * y + z * z);
    float r01 = 2.f * (x * y - w * z);
    float r02 = 2.f * (x * z + w * y);
    float r10 = 2.f * (x * y + w * z);
    float r11 = 1.f - 2.f * (x * x + z * z);
    float r12 = 2.f * (y * z - w * x);
    float r20 = 2.f * (x * z - w * y);
    float r21 = 2.f * (y * z + w * x);
    float r22 = 1.f - 2.f * (x * x + y * y);

    float sx = scales[k * 3 + 0], sy = scales[k * 3 + 1], sz = scales[k * 3 + 2];
    float m00 = r00 * sx, m01 = r01 * sy, m02 = r02 * sz;
    float m10 = r10 * sx, m11 = r11 * sy, m12 = r12 * sz;
    float m20 = r20 * sx, m21 = r21 * sy, m22 = r22 * sz;

    float c00 = m00 * m00 + m01 * m01 + m02 * m02;
    float c01 = m00 * m10 + m01 * m11 + m02 * m12;
    float c11 = m10 * m10 + m11 * m11 + m12 * m12;
    float c02 = m00 * m20 + m01 * m21 + m02 * m22;
    float c12 = m10 * m20 + m11 * m21 + m12 * m22;
    float c22 = m20 * m20 + m21 * m21 + m22 * m22;

    float szz = c22 + EPSF;
    float rx = c02 / szz;
    float ry = c12 / szz;

    float s00 = c00 - c02 * c02 / szz + EPSF;
    float s01 = c01 - c02 * c12 / szz;
    float s11 = c11 - c12 * c12 / szz + EPSF;
    float det = s00 * s11 - s01 * s01;
    float A  = s11 / det;
    float Bc = -s01 / det;
    float D  = s00 / det;

    float a = HL2E * A;
    float b = HL2E * 2.0f * Bc;
    float c = HL2E * D;
    float SA = sqrtf(a);
    float E  = b / (2.0f * SA);
    float Cp = c - E * E;
    if (Cp < 0.0f) Cp = 0.0f;

    float Delta = SA * HPIX;
    float DC = -2.0f * Delta;
    float DD = -Delta * Delta;
    float R  = ex2a(2.0f * DD);

    int safe = (SA <= SA_THIN) ? 1 : 0;

    // block-wide stable partition: safe gaussians first (slice-invariant)
    unsigned bal = __ballot_sync(0xffffffffu, safe);
    unsigned ltmask = (1u << lane) - 1u;
    int w_safe_pre = __popc(bal & ltmask);
    int w_safe_tot = __popc(bal);
    if (lane == 0) wsum[wid] = w_safe_tot;
    __syncthreads();
    int safe_off = 0, n_safe = 0;
#pragma unroll
    for (int u = 0; u < 8; u++) {
        int v2 = wsum[u];
        if (u < wid) safe_off += v2;
        n_safe += v2;
    }
    int thin_off = n_safe + (32 * wid - safe_off);
    int pos = safe ? (safe_off + w_safe_pre)
                   : (thin_off + (lane - w_safe_pre));

    if (t == 0 && s == 0) g_nsafe_pairs[sub] = n_safe >> 1;

    float mz = means[k * 3 + 2];
    float zs = -0.15f + 0.1f * (float)s;
    float zoff = zs - mz;
    float mx = means[k * 3 + 0] + rx * zoff;
    float my = means[k * 3 + 1] + ry * zoff;
    float mask = (fabsf(mz - zs) < md) ? 1.0f : 0.0f;
    float op = opac[k];
    float ft = feat[k];

    int kp = pos >> 1;
    int h  = pos & 1;
    float* tp = stg + kp * 32;
    tp[0  + h] = SA;
    tp[2  + h] = E;
    tp[4  + h] = -SA * mx;
    tp[6  + h] = -Cp;
    tp[8  + h] = -my;
    tp[10 + h] = mask * op;
    tp[12 + h] = mask * op * ft;
    tp[14 + h] = DC;
    tp[16 + h] = DD;
    tp[18 + h] = R;
    __syncthreads();

    // coalesced staging -> global copy (16KB per block)
    const uint4* src4 = reinterpret_cast<const uint4*>(stg);
    uint4* dst4 = reinterpret_cast<uint4*>(
        g_table + (size_t)(s * 16 + sub) * 128 * 32);
#pragma unroll 4
    for (int u = t; u < 1024; u += 256)
        dst4[u] = src4[u];
}

// ---------------------------------------------------------------------------
// Kernel 2: partial render with exp recurrence along 8 contiguous pixels.
// Block = one (slice, subchunk, 8-row tile). 128 threads; 8 contiguous
// pixels per thread. grid = 1024 = 4 slices * 16 subchunks * 16 tiles.
// ---------------------------------------------------------------------------
__global__ void __launch_bounds__(128, 7) k_render_part() {
    __shared__ __align__(16) uint4 smt[1024];   // 128 pairs * 128B = 16KB

    int bid  = blockIdx.x;
    int s    = bid >> 8;
    int sub  = (bid >> 4) & 15;
    int tile = bid & 15;
    int tid  = threadIdx.x;

    const uint4* gsrc = reinterpret_cast<const uint4*>(g_table)
                        + (size_t)(s * 16 + sub) * 128 * 8;
#pragma unroll 8
    for (int t = tid; t < 1024; t += 128)
        smt[t] = __ldg(gsrc + t);
    int nsp = __ldg(&g_nsafe_pairs[sub]);
    __syncthreads();

    int i  = tile * 8 + (tid >> 4);      // row
    int jb = (tid & 15) * 8;             // first col of this thread's 8

    float yv = -1.0f + (float)i * (2.0f / 127.0f);
    float x0 = -1.0f + (float)jb * HPIX;

    uint64_t Y  = pk2(yv, yv);
    uint64_t X0 = pk2(x0, x0);
    const uint64_t SGN = 0x8000000080000000ULL;

    uint64_t S1[8], S2[8];
#pragma unroll
    for (int p = 0; p < 8; p++) { S1[p] = pk2(0.f, 0.f); S2[p] = pk2(0.f, 0.f); }

    const ulonglong2* sp = reinterpret_cast<const ulonglong2*>(smt);

    int kp = 0;
    // ---- safe pairs: 2 exp-pairs per pair-row, multiplicative chain ----
#pragma unroll 2
    for (; kp < nsp; kp++) {
        ulonglong2 u0 = sp[kp * 8 + 0];   // SA | E
        ulonglong2 u1 = sp[kp * 8 + 1];   // SM | NCp
        ulonglong2 u2 = sp[kp * 8 + 2];   // NMY | OP
        ulonglong2 u3 = sp[kp * 8 + 3];   // OFT | DC
        ulonglong2 u4 = sp[kp * 8 + 4];   // DD | R

        uint64_t dy = add2(Y, u2.x);
        uint64_t wv = mul2(mul2(u1.y, dy), dy);   // -Cp*dy^2 <= 0
        uint64_t v  = fma2(u0.x, X0, u1.x);       // SA*x0 + SM
        v = fma2(u0.y, dy, v);                    // + E*dy
        uint64_t nv = v ^ SGN;
        uint64_t q0 = fma2(v, nv, wv);            // -L0
        uint64_t qd = fma2(u3.y, v, u4.x);        // DC*v0 + DD

        float a2, b2, c2, d2;
        upk2(qd, a2, b2);
        a2 = fminf(a2, 88.0f);
        b2 = fminf(b2, 88.0f);
        upk2(q0, c2, d2);
        uint64_t g = pk2(ex2a(c2), ex2a(d2));
        uint64_t d = pk2(ex2a(a2), ex2a(b2));
        uint64_t R = u4.y;

#pragma unroll
        for (int p = 0; p < 8; p++) {
            S2[p] = fma2(g, u2.y, S2[p]);
            uint64_t gg = mul2(g, g);
            S1[p] = fma2(gg, u3.x, S1[p]);
            if (p < 7) {
                g = mul2(g, d);
                d = mul2(d, R);
            }
        }
    }
    // ---- thin pairs: exact ex2 per pixel ----
    for (; kp < 128; kp++) {
        ulonglong2 u0 = sp[kp * 8 + 0];
        ulonglong2 u1 = sp[kp * 8 + 1];
        ulonglong2 u2 = sp[kp * 8 + 2];
        ulonglong2 u3 = sp[kp * 8 + 3];

        uint64_t dy = add2(Y, u2.x);
        uint64_t wv = mul2(mul2(u1.y, dy), dy);
        uint64_t v  = fma2(u0.x, X0, u1.x);
        v = fma2(u0.y, dy, v);
        uint64_t dl = mul2(u3.y, pk2(-0.5f, -0.5f));

#pragma unroll
        for (int p = 0; p < 8; p++) {
            uint64_t nv = v ^ SGN;
            uint64_t q  = fma2(v, nv, wv);
            float l, h;
            upk2(q, l, h);
            uint64_t g = pk2(ex2a(l), ex2a(h));
            S2[p] = fma2(g, u2.y, S2[p]);
            uint64_t gg = mul2(g, g);
            S1[p] = fma2(gg, u3.x, S1[p]);
            v = add2(v, dl);
        }
    }

    // ---- write partials ----
    int p0 = i * 128 + jb;
    float2* dst = g_partial + (size_t)(s * 16 + sub) * 16384;
#pragma unroll
    for (int p = 0; p < 8; p++) {
        float s1l, s1h, s2l, s2h;
        upk2(S1[p], s1l, s1h);
        upk2(S2[p], s2l, s2h);
        dst[p0 + p] = make_float2(s1l + s1h, s2l + s2h);
    }
}

// ---------------------------------------------------------------------------
// Kernel 3: fold. 2 pixels per thread via float4 loads (16 independent
// loads, MLP-16); subchunk pair-adds then exact 4-chunk transmittance
// recurrence (== reference scan). 128 blocks x 256 threads.
// ---------------------------------------------------------------------------
__global__ void __launch_bounds__(256) k_fold(float* __restrict__ out) {
    int g = blockIdx.x * 256 + threadIdx.x;   // 32768
    int s  = g >> 13;
    int pp = g & 8191;                        // pixel pair
    const float4* base = reinterpret_cast<const float4*>(
        g_partial + (size_t)s * 16 * 16384) + pp;

    float img0 = 0.0f, T0 = 1.0f, img1 = 0.0f, T1 = 1.0f;
#pragma unroll
    for (int c = 0; c < 4; c++) {
        float S1a = 0.0f, S2a = 0.0f, S1b = 0.0f, S2b = 0.0f;
#pragma unroll
        for (int u = 0; u < 4; u++) {
            float4 v = __ldg(base + (size_t)(c * 4 + u) * 8192);
            S1a += v.x;  S2a += v.y;
            S1b += v.z;  S2b += v.w;
        }
        img0 = fmaf(T0, S1a, img0);
        T0   = T0 * (1.0f - S2a);
        img1 = fmaf(T1, S1b, img1);
        T1   = T1 * (1.0f - S2b);
    }
    float2* o = reinterpret_cast<float2*>(out + (size_t)s * 16384) + pp;
    *o = make_float2(img0, img1);   // BACKGROUND == 0
}

// ---------------------------------------------------------------------------
extern "C" void kernel_launch(void* const* d_in, const int* in_sizes, int n_in,
                              void* d_out, int out_size) {
    const float* means  = (const float*)d_in[0];
    const float* scales = (const float*)d_in[1];
    const float* rots   = (const float*)d_in[2];
    const float* opac   = (const float*)d_in[3];
    const float* feat   = (const float*)d_in[4];
    float* out = (float*)d_out;

    k_precompute<<<64, 256>>>(means, scales, rots, opac, feat);
    k_render_part<<<1024, 128>>>();
    k_fold<<<128, 256>>>(out);
}

// round 13
// speedup vs baseline: 1.2425x; 1.1246x over previous
#include <cuda_runtime.h>
#include <cstdint>

#define N_GAUSS 4096
#define NSLICE  4
#define EPSF    1e-6f
// +0.5 * log2(e)
#define HL2E    0.72134752044448170367996234050095f
// contiguous pixel x step
#define HPIX    (2.0f / 127.0f)
#define SA_THIN 40.0f

// table: per (slice, subchunk) of 128 pairs, 32 floats per pair (128B line):
// [2e+h]: e0 SA, e1 E, e2 SM(-SA*mx), e3 NCp(-Cp), e4 NMY(-my), e5 OP2(OP/CF),
//         e6 CF(sqrt(OFT)), e7 DC(-2*Delta), e8 DD(-Delta^2), e9 R(2^-2Delta^2)
__device__ __align__(16) float g_table[NSLICE * 16 * 128 * 32];
__device__ int g_nsafe_pairs[16];                 // slice-invariant
__device__ float2 g_partial[NSLICE * 16 * 16384]; // per (slice,sub,pixel)

// ---------------------------------------------------------------------------
__device__ __forceinline__ uint64_t pk2(float lo, float hi) {
    uint64_t r;
    asm("mov.b64 %0, {%1,%2};" : "=l"(r) : "f"(lo), "f"(hi));
    return r;
}
__device__ __forceinline__ void upk2(uint64_t v, float& lo, float& hi) {
    asm("mov.b64 {%0,%1}, %2;" : "=f"(lo), "=f"(hi) : "l"(v));
}
__device__ __forceinline__ uint64_t fma2(uint64_t a, uint64_t b, uint64_t c) {
    uint64_t d;
    asm("fma.rn.f32x2 %0, %1, %2, %3;" : "=l"(d) : "l"(a), "l"(b), "l"(c));
    return d;
}
__device__ __forceinline__ uint64_t mul2(uint64_t a, uint64_t b) {
    uint64_t d;
    asm("mul.rn.f32x2 %0, %1, %2;" : "=l"(d) : "l"(a), "l"(b));
    return d;
}
__device__ __forceinline__ uint64_t add2(uint64_t a, uint64_t b) {
    uint64_t d;
    asm("add.rn.f32x2 %0, %1, %2;" : "=l"(d) : "l"(a), "l"(b));
    return d;
}
__device__ __forceinline__ float ex2a(float x) {
    float r;
    asm("ex2.approx.f32 %0, %1;" : "=f"(r) : "f"(x));
    return r;
}

// ---------------------------------------------------------------------------
// Kernel 1: precompute. 64 blocks = (slice, subchunk), 256 threads = one
// gaussian each. Coefficients staged in smem -> coalesced uint4 writes.
// ---------------------------------------------------------------------------
__global__ void __launch_bounds__(256) k_precompute(
        const float* __restrict__ means,
        const float* __restrict__ scales,
        const float* __restrict__ rot,
        const float* __restrict__ opac,
        const float* __restrict__ feat) {
    __shared__ float red[8];
    __shared__ int wsum[8];
    __shared__ __align__(16) float stg[128 * 32];   // 16KB staging tile

    int s   = blockIdx.x >> 4;
    int sub = blockIdx.x & 15;
    int t   = threadIdx.x;
    int lane = t & 31;
    int wid  = t >> 5;

    // zero staging (pads must be deterministic)
    {
        uint4 z = make_uint4(0, 0, 0, 0);
        uint4* sz4 = reinterpret_cast<uint4*>(stg);
#pragma unroll 4
        for (int u = t; u < 1024; u += 256) sz4[u] = z;
    }

    // block-local max over all 4096 z-scales
    {
        float m = 0.0f;
        for (int k = t; k < N_GAUSS; k += 256)
            m = fmaxf(m, __ldg(&scales[k * 3 + 2]));
#pragma unroll
        for (int o = 16; o > 0; o >>= 1)
            m = fmaxf(m, __shfl_xor_sync(0xffffffffu, m, o));
        if (lane == 0) red[wid] = m;
    }
    __syncthreads();
    float md = red[0];
#pragma unroll
    for (int u = 1; u < 8; u++) md = fmaxf(md, red[u]);
    md *= 3.0f;

    int k = sub * 256 + t;

    float4 q4 = __ldg(reinterpret_cast<const float4*>(rot) + k);
    float inq = rsqrtf(q4.x * q4.x + q4.y * q4.y + q4.z * q4.z + q4.w * q4.w);
    float w = q4.x * inq, x = q4.y * inq, y = q4.z * inq, z = q4.w * inq;

    float r00 = 1.f - 2.f * (y * y + z * z);
    float r01 = 2.f * (x * y - w * z);
    float r02 = 2.f * (x * z + w * y);
    float r10 = 2.f * (x * y + w * z);
    float r11 = 1.f - 2.f * (x * x + z * z);
    float r12 = 2.f * (y * z - w * x);
    float r20 = 2.f * (x * z - w * y);
    float r21 = 2.f * (y * z + w * x);
    float r22 = 1.f - 2.f * (x * x + y * y);

    float sx = scales[k * 3 + 0], sy = scales[k * 3 + 1], sz = scales[k * 3 + 2];
    float m00 = r00 * sx, m01 = r01 * sy, m02 = r02 * sz;
    float m10 = r10 * sx, m11 = r11 * sy, m12 = r12 * sz;
    float m20 = r20 * sx, m21 = r21 * sy, m22 = r22 * sz;

    float c00 = m00 * m00 + m01 * m01 + m02 * m02;
    float c01 = m00 * m10 + m01 * m11 + m02 * m12;
    float c11 = m10 * m10 + m11 * m11 + m12 * m12;
    float c02 = m00 * m20 + m01 * m21 + m02 * m22;
    float c12 = m10 * m20 + m11 * m21 + m12 * m22;
    float c22 = m20 * m20 + m21 * m21 + m22 * m22;

    float szz = c22 + EPSF;
    float rx = c02 / szz;
    float ry = c12 / szz;

    float s00 = c00 - c02 * c02 / szz + EPSF;
    float s01 = c01 - c02 * c12 / szz;
    float s11 = c11 - c12 * c12 / szz + EPSF;
    float det = s00 * s11 - s01 * s01;
    float A  = s11 / det;
    float Bc = -s01 / det;
    float D  = s00 / det;

    float a = HL2E * A;
    float b = HL2E * 2.0f * Bc;
    float c = HL2E * D;
    float SA = sqrtf(a);
    float E  = b / (2.0f * SA);
    float Cp = c - E * E;
    if (Cp < 0.0f) Cp = 0.0f;

    float Delta = SA * HPIX;
    float DC = -2.0f * Delta;
    float DD = -Delta * Delta;
    float R  = ex2a(2.0f * DD);

    int safe = (SA <= SA_THIN) ? 1 : 0;

    // block-wide stable partition: safe gaussians first (slice-invariant)
    unsigned bal = __ballot_sync(0xffffffffu, safe);
    unsigned ltmask = (1u << lane) - 1u;
    int w_safe_pre = __popc(bal & ltmask);
    int w_safe_tot = __popc(bal);
    if (lane == 0) wsum[wid] = w_safe_tot;
    __syncthreads();
    int safe_off = 0, n_safe = 0;
#pragma unroll
    for (int u = 0; u < 8; u++) {
        int v2 = wsum[u];
        if (u < wid) safe_off += v2;
        n_safe += v2;
    }
    int thin_off = n_safe + (32 * wid - safe_off);
    int pos = safe ? (safe_off + w_safe_pre)
                   : (thin_off + (lane - w_safe_pre));

    if (t == 0 && s == 0) g_nsafe_pairs[sub] = n_safe >> 1;

    float mz = means[k * 3 + 2];
    float zs = -0.15f + 0.1f * (float)s;
    float zoff = zs - mz;
    float mx = means[k * 3 + 0] + rx * zoff;
    float my = means[k * 3 + 1] + ry * zoff;
    float mask = (fabsf(mz - zs) < md) ? 1.0f : 0.0f;
    float op = opac[k];
    float ft = feat[k];

    float OP  = mask * op;
    float OFT = mask * op * ft;
    // sqrt-folding: h = g*CF accumulates S1 via fma(h,h,S1);
    // S2 via fma(h, OP2, S2) with OP2 = OP/CF (CF cancels).
    float CF  = sqrtf(fmaxf(OFT, 1e-26f));
    float OP2 = OP / CF;

    int kp = pos >> 1;
    int h  = pos & 1;
    float* tp = stg + kp * 32;
    tp[0  + h] = SA;
    tp[2  + h] = E;
    tp[4  + h] = -SA * mx;
    tp[6  + h] = -Cp;
    tp[8  + h] = -my;
    tp[10 + h] = OP2;
    tp[12 + h] = CF;
    tp[14 + h] = DC;
    tp[16 + h] = DD;
    tp[18 + h] = R;
    __syncthreads();

    // coalesced staging -> global copy (16KB per block)
    const uint4* src4 = reinterpret_cast<const uint4*>(stg);
    uint4* dst4 = reinterpret_cast<uint4*>(
        g_table + (size_t)(s * 16 + sub) * 128 * 32);
#pragma unroll 4
    for (int u = t; u < 1024; u += 256)
        dst4[u] = src4[u];
}

// ---------------------------------------------------------------------------
// Kernel 2: partial render with exp recurrence along 8 contiguous pixels.
// Block = one (slice, subchunk, 8-row tile). 128 threads; 8 contiguous
// pixels per thread. Inner loop: 4 packed ops/pixel (S2 fma, S1 fma(h,h),
// chain h*=d, d*=R). grid = 1024 = 4 slices * 16 subchunks * 16 tiles.
// ---------------------------------------------------------------------------
__global__ void __launch_bounds__(128, 7) k_render_part() {
    __shared__ __align__(16) uint4 smt[1024];   // 128 pairs * 128B = 16KB

    int bid  = blockIdx.x;
    int s    = bid >> 8;
    int sub  = (bid >> 4) & 15;
    int tile = bid & 15;
    int tid  = threadIdx.x;

    const uint4* gsrc = reinterpret_cast<const uint4*>(g_table)
                        + (size_t)(s * 16 + sub) * 128 * 8;
#pragma unroll 8
    for (int t = tid; t < 1024; t += 128)
        smt[t] = __ldg(gsrc + t);
    int nsp = __ldg(&g_nsafe_pairs[sub]);
    __syncthreads();

    int i  = tile * 8 + (tid >> 4);      // row
    int jb = (tid & 15) * 8;             // first col of this thread's 8

    float yv = -1.0f + (float)i * (2.0f / 127.0f);
    float x0 = -1.0f + (float)jb * HPIX;

    uint64_t Y  = pk2(yv, yv);
    uint64_t X0 = pk2(x0, x0);
    const uint64_t SGN = 0x8000000080000000ULL;

    uint64_t S1[8], S2[8];
#pragma unroll
    for (int p = 0; p < 8; p++) { S1[p] = pk2(0.f, 0.f); S2[p] = pk2(0.f, 0.f); }

    const ulonglong2* sp = reinterpret_cast<const ulonglong2*>(smt);

    int kp = 0;
    // ---- safe pairs: 2 exp-pairs per pair-row, multiplicative chain ----
#pragma unroll 2
    for (; kp < nsp; kp++) {
        ulonglong2 u0 = sp[kp * 8 + 0];   // SA | E
        ulonglong2 u1 = sp[kp * 8 + 1];   // SM | NCp
        ulonglong2 u2 = sp[kp * 8 + 2];   // NMY | OP2
        ulonglong2 u3 = sp[kp * 8 + 3];   // CF | DC
        ulonglong2 u4 = sp[kp * 8 + 4];   // DD | R

        uint64_t dy = add2(Y, u2.x);
        uint64_t wv = mul2(mul2(u1.y, dy), dy);   // -Cp*dy^2 <= 0
        uint64_t v  = fma2(u0.x, X0, u1.x);       // SA*x0 + SM
        v = fma2(u0.y, dy, v);                    // + E*dy
        uint64_t nv = v ^ SGN;
        uint64_t q0 = fma2(v, nv, wv);            // -L0
        uint64_t qd = fma2(u3.y, v, u4.x);        // DC*v0 + DD

        float a2, b2, c2, d2;
        upk2(qd, a2, b2);
        a2 = fminf(a2, 88.0f);
        b2 = fminf(b2, 88.0f);
        upk2(q0, c2, d2);
        uint64_t g = pk2(ex2a(c2), ex2a(d2));
        uint64_t d = pk2(ex2a(a2), ex2a(b2));
        uint64_t h = mul2(g, u3.x);               // h0 = g0*CF
        uint64_t R = u4.y;

#pragma unroll
        for (int p = 0; p < 8; p++) {
            S2[p] = fma2(h, u2.y, S2[p]);         // += g*OP
            S1[p] = fma2(h, h, S1[p]);            // += g^2*OFT
            if (p < 7) {
                h = mul2(h, d);
                d = mul2(d, R);
            }
        }
    }
    // ---- thin pairs: exact ex2 per pixel ----
    for (; kp < 128; kp++) {
        ulonglong2 u0 = sp[kp * 8 + 0];
        ulonglong2 u1 = sp[kp * 8 + 1];
        ulonglong2 u2 = sp[kp * 8 + 2];
        ulonglong2 u3 = sp[kp * 8 + 3];

        uint64_t dy = add2(Y, u2.x);
        uint64_t wv = mul2(mul2(u1.y, dy), dy);
        uint64_t v  = fma2(u0.x, X0, u1.x);
        v = fma2(u0.y, dy, v);
        uint64_t dl = mul2(u3.y, pk2(-0.5f, -0.5f));  // Delta = -DC/2

#pragma unroll
        for (int p = 0; p < 8; p++) {
            uint64_t nv = v ^ SGN;
            uint64_t q  = fma2(v, nv, wv);
            float l, hh;
            upk2(q, l, hh);
            uint64_t g = pk2(ex2a(l), ex2a(hh));
            uint64_t h = mul2(g, u3.x);           // h = g*CF
            S2[p] = fma2(h, u2.y, S2[p]);
            S1[p] = fma2(h, h, S1[p]);
            v = add2(v, dl);
        }
    }

    // ---- write partials ----
    int p0 = i * 128 + jb;
    float2* dst = g_partial + (size_t)(s * 16 + sub) * 16384;
#pragma unroll
    for (int p = 0; p < 8; p++) {
        float s1l, s1h, s2l, s2h;
        upk2(S1[p], s1l, s1h);
        upk2(S2[p], s2l, s2h);
        dst[p0 + p] = make_float2(s1l + s1h, s2l + s2h);
    }
}

// ---------------------------------------------------------------------------
// Kernel 3: fold. 2 pixels per thread via float4 loads (MLP-16);
// subchunk adds then exact 4-chunk transmittance recurrence.
// ---------------------------------------------------------------------------
__global__ void __launch_bounds__(256) k_fold(float* __restrict__ out) {
    int g = blockIdx.x * 256 + threadIdx.x;   // 32768
    int s  = g >> 13;
    int pp = g & 8191;                        // pixel pair
    const float4* base = reinterpret_cast<const float4*>(
        g_partial + (size_t)s * 16 * 16384) + pp;

    float img0 = 0.0f, T0 = 1.0f, img1 = 0.0f, T1 = 1.0f;
#pragma unroll
    for (int c = 0; c < 4; c++) {
        float S1a = 0.0f, S2a = 0.0f, S1b = 0.0f, S2b = 0.0f;
#pragma unroll
        for (int u = 0; u < 4; u++) {
            float4 v = __ldg(base + (size_t)(c * 4 + u) * 8192);
            S1a += v.x;  S2a += v.y;
            S1b += v.z;  S2b += v.w;
        }
        img0 = fmaf(T0, S1a, img0);
        T0   = T0 * (1.0f - S2a);
        img1 = fmaf(T1, S1b, img1);
        T1   = T1 * (1.0f - S2b);
    }
    float2* o = reinterpret_cast<float2*>(out + (size_t)s * 16384) + pp;
    *o = make_float2(img0, img1);   // BACKGROUND == 0
}

// ---------------------------------------------------------------------------
extern "C" void kernel_launch(void* const* d_in, const int* in_sizes, int n_in,
                              void* d_out, int out_size) {
    const float* means  = (const float*)d_in[0];
    const float* scales = (const float*)d_in[1];
    const float* rots   = (const float*)d_in[2];
    const float* opac   = (const float*)d_in[3];
    const float* feat   = (const float*)d_in[4];
    float* out = (float*)d_out;

    k_precompute<<<64, 256>>>(means, scales, rots, opac, feat);
    k_render_part<<<1024, 128>>>();
    k_fold<<<128, 256>>>(out);
}

// round 14
// speedup vs baseline: 1.2479x; 1.0044x over previous
#include <cuda_runtime.h>
#include <cstdint>

#define N_GAUSS 4096
#define NSLICE  4
#define EPSF    1e-6f
// +0.5 * log2(e)
#define HL2E    0.72134752044448170367996234050095f
// contiguous pixel x step
#define HPIX    (2.0f / 127.0f)
#define SA_THIN 40.0f

// table: per (slice, subchunk) of 128 pairs, 32 floats per pair (128B line):
// [2e+h]: e0 SA, e1 E, e2 SM(-SA*mx), e3 NCp(-Cp), e4 NMY(-my), e5 OP2(OP/CF),
//         e6 LCF(log2 CF), e7 DC(-2*Delta), e8 DD(-Delta^2), e9 R(2^-2Delta^2)
__device__ __align__(16) float g_table[NSLICE * 16 * 128 * 32];
__device__ int g_nsafe_pairs[16];                 // slice-invariant
__device__ float2 g_partial[NSLICE * 16 * 16384]; // per (slice,sub,pixel)

// ---------------------------------------------------------------------------
__device__ __forceinline__ uint64_t pk2(float lo, float hi) {
    uint64_t r;
    asm("mov.b64 %0, {%1,%2};" : "=l"(r) : "f"(lo), "f"(hi));
    return r;
}
__device__ __forceinline__ void upk2(uint64_t v, float& lo, float& hi) {
    asm("mov.b64 {%0,%1}, %2;" : "=f"(lo), "=f"(hi) : "l"(v));
}
__device__ __forceinline__ uint64_t fma2(uint64_t a, uint64_t b, uint64_t c) {
    uint64_t d;
    asm("fma.rn.f32x2 %0, %1, %2, %3;" : "=l"(d) : "l"(a), "l"(b), "l"(c));
    return d;
}
__device__ __forceinline__ uint64_t mul2(uint64_t a, uint64_t b) {
    uint64_t d;
    asm("mul.rn.f32x2 %0, %1, %2;" : "=l"(d) : "l"(a), "l"(b));
    return d;
}
__device__ __forceinline__ uint64_t add2(uint64_t a, uint64_t b) {
    uint64_t d;
    asm("add.rn.f32x2 %0, %1, %2;" : "=l"(d) : "l"(a), "l"(b));
    return d;
}
__device__ __forceinline__ float ex2a(float x) {
    float r;
    asm("ex2.approx.f32 %0, %1;" : "=f"(r) : "f"(x));
    return r;
}

// ---------------------------------------------------------------------------
// Kernel 1: precompute. 64 blocks = (slice, subchunk), 256 threads = one
// gaussian each. All global input loads hoisted ahead of the max-reduction
// so their latencies overlap (kernel is latency-bound at 64 blocks).
// Coefficients staged in smem -> coalesced uint4 writes.
// ---------------------------------------------------------------------------
__global__ void __launch_bounds__(256) k_precompute(
        const float* __restrict__ means,
        const float* __restrict__ scales,
        const float* __restrict__ rot,
        const float* __restrict__ opac,
        const float* __restrict__ feat) {
    __shared__ float red[8];
    __shared__ int wsum[8];
    __shared__ __align__(16) float stg[128 * 32];   // 16KB staging tile

    int s   = blockIdx.x >> 4;
    int sub = blockIdx.x & 15;
    int t   = threadIdx.x;
    int lane = t & 31;
    int wid  = t >> 5;

    int k = sub * 256 + t;

    // ---- hoisted global loads (issue all up front) ----
    float4 q4 = __ldg(reinterpret_cast<const float4*>(rot) + k);
    float sx = __ldg(&scales[k * 3 + 0]);
    float sy = __ldg(&scales[k * 3 + 1]);
    float sz = __ldg(&scales[k * 3 + 2]);
    float mx0 = __ldg(&means[k * 3 + 0]);
    float my0 = __ldg(&means[k * 3 + 1]);
    float mz  = __ldg(&means[k * 3 + 2]);
    float op = __ldg(&opac[k]);
    float ft = __ldg(&feat[k]);

    // zero staging (pads must be deterministic)
    {
        uint4 z = make_uint4(0, 0, 0, 0);
        uint4* sz4 = reinterpret_cast<uint4*>(stg);
#pragma unroll 4
        for (int u = t; u < 1024; u += 256) sz4[u] = z;
    }

    // block-local max over all 4096 z-scales
    {
        float m = 0.0f;
        for (int kk = t; kk < N_GAUSS; kk += 256)
            m = fmaxf(m, __ldg(&scales[kk * 3 + 2]));
#pragma unroll
        for (int o = 16; o > 0; o >>= 1)
            m = fmaxf(m, __shfl_xor_sync(0xffffffffu, m, o));
        if (lane == 0) red[wid] = m;
    }
    __syncthreads();
    float md = red[0];
#pragma unroll
    for (int u = 1; u < 8; u++) md = fmaxf(md, red[u]);
    md *= 3.0f;

    float inq = rsqrtf(q4.x * q4.x + q4.y * q4.y + q4.z * q4.z + q4.w * q4.w);
    float w = q4.x * inq, x = q4.y * inq, y = q4.z * inq, z = q4.w * inq;

    float r00 = 1.f - 2.f * (y * y + z * z);
    float r01 = 2.f * (x * y - w * z);
    float r02 = 2.f * (x * z + w * y);
    float r10 = 2.f * (x * y + w * z);
    float r11 = 1.f - 2.f * (x * x + z * z);
    float r12 = 2.f * (y * z - w * x);
    float r20 = 2.f * (x * z - w * y);
    float r21 = 2.f * (y * z + w * x);
    float r22 = 1.f - 2.f * (x * x + y * y);

    float m00 = r00 * sx, m01 = r01 * sy, m02 = r02 * sz;
    float m10 = r10 * sx, m11 = r11 * sy, m12 = r12 * sz;
    float m20 = r20 * sx, m21 = r21 * sy, m22 = r22 * sz;

    float c00 = m00 * m00 + m01 * m01 + m02 * m02;
    float c01 = m00 * m10 + m01 * m11 + m02 * m12;
    float c11 = m10 * m10 + m11 * m11 + m12 * m12;
    float c02 = m00 * m20 + m01 * m21 + m02 * m22;
    float c12 = m10 * m20 + m11 * m21 + m12 * m22;
    float c22 = m20 * m20 + m21 * m21 + m22 * m22;

    float szz = c22 + EPSF;
    float rx = c02 / szz;
    float ry = c12 / szz;

    float s00 = c00 - c02 * c02 / szz + EPSF;
    float s01 = c01 - c02 * c12 / szz;
    float s11 = c11 - c12 * c12 / szz + EPSF;
    float det = s00 * s11 - s01 * s01;
    float A  = s11 / det;
    float Bc = -s01 / det;
    float D  = s00 / det;

    float a = HL2E * A;
    float b = HL2E * 2.0f * Bc;
    float c = HL2E * D;
    float SA = sqrtf(a);
    float E  = b / (2.0f * SA);
    float Cp = c - E * E;
    if (Cp < 0.0f) Cp = 0.0f;

    float Delta = SA * HPIX;
    float DC = -2.0f * Delta;
    float DD = -Delta * Delta;
    float R  = ex2a(2.0f * DD);

    int safe = (SA <= SA_THIN) ? 1 : 0;

    // block-wide stable partition: safe gaussians first (slice-invariant)
    unsigned bal = __ballot_sync(0xffffffffu, safe);
    unsigned ltmask = (1u << lane) - 1u;
    int w_safe_pre = __popc(bal & ltmask);
    int w_safe_tot = __popc(bal);
    if (lane == 0) wsum[wid] = w_safe_tot;
    __syncthreads();
    int safe_off = 0, n_safe = 0;
#pragma unroll
    for (int u = 0; u < 8; u++) {
        int v2 = wsum[u];
        if (u < wid) safe_off += v2;
        n_safe += v2;
    }
    int thin_off = n_safe + (32 * wid - safe_off);
    int pos = safe ? (safe_off + w_safe_pre)
                   : (thin_off + (lane - w_safe_pre));

    if (t == 0 && s == 0) g_nsafe_pairs[sub] = n_safe >> 1;

    float zs = -0.15f + 0.1f * (float)s;
    float zoff = zs - mz;
    float mx = mx0 + rx * zoff;
    float my = my0 + ry * zoff;
    float mask = (fabsf(mz - zs) < md) ? 1.0f : 0.0f;

    float OP  = mask * op;
    float OFT = mask * op * ft;
    // sqrt-folding + log-fold: h = 2^(q0 + LCF) accumulates S1 via fma(h,h);
    // S2 via fma(h, OP2) with OP2 = OP/CF.
    float CF  = sqrtf(fmaxf(OFT, 1e-26f));
    float LCF = log2f(CF);
    float OP2 = OP / CF;

    int kp = pos >> 1;
    int h  = pos & 1;
    float* tp = stg + kp * 32;
    tp[0  + h] = SA;
    tp[2  + h] = E;
    tp[4  + h] = -SA * mx;
    tp[6  + h] = -Cp;
    tp[8  + h] = -my;
    tp[10 + h] = OP2;
    tp[12 + h] = LCF;
    tp[14 + h] = DC;
    tp[16 + h] = DD;
    tp[18 + h] = R;
    __syncthreads();

    // coalesced staging -> global copy (16KB per block)
    const uint4* src4 = reinterpret_cast<const uint4*>(stg);
    uint4* dst4 = reinterpret_cast<uint4*>(
        g_table + (size_t)(s * 16 + sub) * 128 * 32);
#pragma unroll 4
    for (int u = t; u < 1024; u += 256)
        dst4[u] = src4[u];
}

// ---------------------------------------------------------------------------
// Kernel 2: partial render with exp recurrence along 8 contiguous pixels.
// Block = one (slice, subchunk, 8-row tile). 128 threads; 8 contiguous
// pixels per thread. LCF folded into wv so h = ex2(q0) directly.
// grid = 1024 = 4 slices * 16 subchunks * 16 tiles.
// ---------------------------------------------------------------------------
__global__ void __launch_bounds__(128, 7) k_render_part() {
    __shared__ __align__(16) uint4 smt[1024];   // 128 pairs * 128B = 16KB

    int bid  = blockIdx.x;
    int s    = bid >> 8;
    int sub  = (bid >> 4) & 15;
    int tile = bid & 15;
    int tid  = threadIdx.x;

    const uint4* gsrc = reinterpret_cast<const uint4*>(g_table)
                        + (size_t)(s * 16 + sub) * 128 * 8;
#pragma unroll 8
    for (int t = tid; t < 1024; t += 128)
        smt[t] = __ldg(gsrc + t);
    int nsp = __ldg(&g_nsafe_pairs[sub]);
    __syncthreads();

    int i  = tile * 8 + (tid >> 4);      // row
    int jb = (tid & 15) * 8;             // first col of this thread's 8

    float yv = -1.0f + (float)i * (2.0f / 127.0f);
    float x0 = -1.0f + (float)jb * HPIX;

    uint64_t Y  = pk2(yv, yv);
    uint64_t X0 = pk2(x0, x0);
    const uint64_t SGN = 0x8000000080000000ULL;

    uint64_t S1[8], S2[8];
#pragma unroll
    for (int p = 0; p < 8; p++) { S1[p] = pk2(0.f, 0.f); S2[p] = pk2(0.f, 0.f); }

    const ulonglong2* sp = reinterpret_cast<const ulonglong2*>(smt);

    int kp = 0;
    // ---- safe pairs: 2 exp-pairs per pair-row, multiplicative chain ----
#pragma unroll 2
    for (; kp < nsp; kp++) {
        ulonglong2 u0 = sp[kp * 8 + 0];   // SA | E
        ulonglong2 u1 = sp[kp * 8 + 1];   // SM | NCp
        ulonglong2 u2 = sp[kp * 8 + 2];   // NMY | OP2
        ulonglong2 u3 = sp[kp * 8 + 3];   // LCF | DC
        ulonglong2 u4 = sp[kp * 8 + 4];   // DD | R

        uint64_t dy = add2(Y, u2.x);
        uint64_t wv = fma2(mul2(u1.y, dy), dy, u3.x); // -Cp*dy^2 + LCF
        uint64_t v  = fma2(u0.x, X0, u1.x);           // SA*x0 + SM
        v = fma2(u0.y, dy, v);                        // + E*dy
        uint64_t nv = v ^ SGN;
        uint64_t q0 = fma2(v, nv, wv);                // -L0 + LCF
        uint64_t qd = fma2(u3.y, v, u4.x);            // DC*v0 + DD

        float a2, b2, c2, d2;
        upk2(qd, a2, b2);
        a2 = fminf(a2, 88.0f);
        b2 = fminf(b2, 88.0f);
        upk2(q0, c2, d2);
        uint64_t h = pk2(ex2a(c2), ex2a(d2));         // h0 = g0*CF
        uint64_t d = pk2(ex2a(a2), ex2a(b2));
        uint64_t R = u4.y;

#pragma unroll
        for (int p = 0; p < 8; p++) {
            S2[p] = fma2(h, u2.y, S2[p]);             // += g*OP
            S1[p] = fma2(h, h, S1[p]);                // += g^2*OFT
            if (p < 7) {
                h = mul2(h, d);
                d = mul2(d, R);
            }
        }
    }
    // ---- thin pairs: exact ex2 per pixel ----
    for (; kp < 128; kp++) {
        ulonglong2 u0 = sp[kp * 8 + 0];
        ulonglong2 u1 = sp[kp * 8 + 1];
        ulonglong2 u2 = sp[kp * 8 + 2];
        ulonglong2 u3 = sp[kp * 8 + 3];

        uint64_t dy = add2(Y, u2.x);
        uint64_t wv = fma2(mul2(u1.y, dy), dy, u3.x); // -Cp*dy^2 + LCF
        uint64_t v  = fma2(u0.x, X0, u1.x);
        v = fma2(u0.y, dy, v);
        uint64_t dl = mul2(u3.y, pk2(-0.5f, -0.5f));  // Delta = -DC/2

#pragma unroll
        for (int p = 0; p < 8; p++) {
            uint64_t nv = v ^ SGN;
            uint64_t q  = fma2(v, nv, wv);            // -L + LCF
            float l, hh;
            upk2(q, l, hh);
            uint64_t h = pk2(ex2a(l), ex2a(hh));      // h = g*CF
            S2[p] = fma2(h, u2.y, S2[p]);
            S1[p] = fma2(h, h, S1[p]);
            v = add2(v, dl);
        }
    }

    // ---- write partials ----
    int p0 = i * 128 + jb;
    float2* dst = g_partial + (size_t)(s * 16 + sub) * 16384;
#pragma unroll
    for (int p = 0; p < 8; p++) {
        float s1l, s1h, s2l, s2h;
        upk2(S1[p], s1l, s1h);
        upk2(S2[p], s2l, s2h);
        dst[p0 + p] = make_float2(s1l + s1h, s2l + s2h);
    }
}

// ---------------------------------------------------------------------------
// Kernel 3: fold. 2 pixels per thread via float4 loads (MLP-16);
// subchunk adds then exact 4-chunk transmittance recurrence.
// ---------------------------------------------------------------------------
__global__ void __launch_bounds__(256) k_fold(float* __restrict__ out) {
    int g = blockIdx.x * 256 + threadIdx.x;   // 32768
    int s  = g >> 13;
    int pp = g & 8191;                        // pixel pair
    const float4* base = reinterpret_cast<const float4*>(
        g_partial + (size_t)s * 16 * 16384) + pp;

    float img0 = 0.0f, T0 = 1.0f, img1 = 0.0f, T1 = 1.0f;
#pragma unroll
    for (int c = 0; c < 4; c++) {
        float S1a = 0.0f, S2a = 0.0f, S1b = 0.0f, S2b = 0.0f;
#pragma unroll
        for (int u = 0; u < 4; u++) {
            float4 v = __ldg(base + (size_t)(c * 4 + u) * 8192);
            S1a += v.x;  S2a += v.y;
            S1b += v.z;  S2b += v.w;
        }
        img0 = fmaf(T0, S1a, img0);
        T0   = T0 * (1.0f - S2a);
        img1 = fmaf(T1, S1b, img1);
        T1   = T1 * (1.0f - S2b);
    }
    float2* o = reinterpret_cast<float2*>(out + (size_t)s * 16384) + pp;
    *o = make_float2(img0, img1);   // BACKGROUND == 0
}

// ---------------------------------------------------------------------------
extern "C" void kernel_launch(void* const* d_in, const int* in_sizes, int n_in,
                              void* d_out, int out_size) {
    const float* means  = (const float*)d_in[0];
    const float* scales = (const float*)d_in[1];
    const float* rots   = (const float*)d_in[2];
    const float* opac   = (const float*)d_in[3];
    const float* feat   = (const float*)d_in[4];
    float* out = (float*)d_out;

    k_precompute<<<64, 256>>>(means, scales, rots, opac, feat);
    k_render_part<<<1024, 128>>>();
    k_fold<<<128, 256>>>(out);
}